// round 14
// baseline (speedup 1.0000x reference)
#include <cuda_runtime.h>
#include <cuda_fp16.h>
#include <cstdint>

#define S_DIM 128
#define I_DIM 256
#define CM    256
#define CC    32
#define CZ    128
#define M1    8192   // I_DIM * CC
#define NROWS 32768  // S_DIM * I_DIM

// Scratch (device globals: allocation-free per harness rules)
__device__ __half g_Ah[(size_t)M1 * S_DIM];     // [(i,c)][s]  A/128, fp16
__device__ __half g_Bh[(size_t)M1 * S_DIM];     // [(j,d)][s]  B,     fp16
__device__ __half g_S16[(size_t)M1 * M1];       // outer [(i,c)][(j,d)], fp16
__device__ __half g_woT[CZ * 1024];             // [z][(c,d)] fp16 transposed w_out
__device__ __half g_WlrT[64 * CM];              // [col(0..63)][k] fp16 (wl|wr)^T

// ---------------------------------------------------------------------------
// helpers
// ---------------------------------------------------------------------------
__device__ __forceinline__ void cp16(void* s, const void* g) {
    unsigned sa = (unsigned)__cvta_generic_to_shared(s);
    asm volatile("cp.async.cg.shared.global [%0], [%1], 16;\n" :: "r"(sa), "l"(g));
}
__device__ __forceinline__ void cp_commit() { asm volatile("cp.async.commit_group;\n"); }
template<int N> __device__ __forceinline__ void cp_wait() {
    asm volatile("cp.async.wait_group %0;\n" :: "n"(N));
}

__device__ __forceinline__ void ldsm4(unsigned& r0, unsigned& r1, unsigned& r2, unsigned& r3,
                                      unsigned addr) {
    asm volatile("ldmatrix.sync.aligned.m8n8.x4.shared.b16 {%0,%1,%2,%3}, [%4];"
        : "=r"(r0), "=r"(r1), "=r"(r2), "=r"(r3) : "r"(addr));
}

__device__ __forceinline__ void mma_f16(float c[4],
                                        unsigned a0, unsigned a1, unsigned a2, unsigned a3,
                                        unsigned b0, unsigned b1) {
    asm volatile(
        "mma.sync.aligned.m16n8k16.row.col.f32.f16.f16.f32 "
        "{%0,%1,%2,%3}, {%4,%5,%6,%7}, {%8,%9}, {%0,%1,%2,%3};"
        : "+f"(c[0]), "+f"(c[1]), "+f"(c[2]), "+f"(c[3])
        : "r"(a0), "r"(a1), "r"(a2), "r"(a3), "r"(b0), "r"(b1));
}

__device__ __forceinline__ unsigned packh2(float a, float b) {
    __half2 h = __floats2half2_rn(a, b);
    return *(unsigned*)&h;
}

// ---------------------------------------------------------------------------
// Kernel 0 (prep): w_out transpose + (wl|wr) transpose only.
//   blocks [0,128): woT, z = bid; blocks [128,136): WlrT.
// ---------------------------------------------------------------------------
__global__ __launch_bounds__(256) void k_prep(
    const float* __restrict__ wo,
    const float* __restrict__ wl, const float* __restrict__ wr)
{
    const int bid = blockIdx.x;
    const int tid = threadIdx.x;
    if (bid < 128) {
        const int z = bid;
        for (int k = tid; k < 1024; k += 256)
            g_woT[z * 1024 + k] = __float2half(wo[k * CZ + z]);
    } else {
        const int base = (bid - 128) * 2048;
        for (int t = tid; t < 2048; t += 256) {
            int e = base + t;
            int c = e >> 8, k = e & 255;
            float v = (c < 32) ? wl[k * CC + c] : wr[k * CC + (c - 32)];
            g_WlrT[c * CM + k] = __float2half(v);
        }
    }
}

// ---------------------------------------------------------------------------
// Kernel 1: fused LN stats + LN + dual projection (fp16 m16n8k16).
//   CTA: fixed i, 64 consecutive s. Full 64x256 x tile resident in smem;
//   stats computed in-CTA (x read from DRAM exactly once program-wide).
//   smem: Wt [64][264] halves (33792 B) + X [64][260] floats (66560 B)
//         + lnw/lnb (2048 B) + mu/rs (512 B)  -> 102912 B, 2 CTAs/SM.
// ---------------------------------------------------------------------------
#define WT_PITCH 264   // halves per Wt row
#define X_PITCH  260   // floats per X row

__global__ __launch_bounds__(128, 2) void k_proj(
    const float* __restrict__ x, const float* __restrict__ lnw, const float* __restrict__ lnb,
    const float* __restrict__ bl, const float* __restrict__ br)
{
    extern __shared__ char smc[];
    __half* Wt   = (__half*)smc;                          // 33792 B
    float*  X    = (float*)(smc + 33792);                 // [64][260] floats
    float*  lnws = (float*)(smc + 33792 + 66560);         // 256
    float*  lnbs = lnws + 256;                            // 256
    float*  mus_s = lnbs + 256;                           // 64
    float*  rss_s = mus_s + 64;                           // 64

    const int tid  = threadIdx.x;
    const int warp = tid >> 5, lane = tid & 31;
    const int g = lane >> 2, q = lane & 3;
    const int wm = (warp >> 1) * 32, wn = (warp & 1) * 32;
    const int m0 = blockIdx.x * 64;
    const int i  = m0 >> 7;
    const int s0 = m0 & 127;

    // stage Wt (2048 cp16) and full X tile (4096 cp16)
    #pragma unroll
    for (int it = 0; it < 16; it++) {
        int v = tid + it * 128;                 // 0..2047
        int row = v >> 5, seg = v & 31;
        cp16(&Wt[row * WT_PITCH + seg * 8], &g_WlrT[row * CM + seg * 8]);
    }
    #pragma unroll
    for (int it = 0; it < 32; it++) {
        int v = tid + it * 128;                 // 0..4095
        int r = v >> 6, k4 = (v & 63) << 2;
        cp16(&X[r * X_PITCH + k4],
             &x[(size_t)((s0 + r) * 256 + i) * CM + k4]);
    }
    cp_commit();
    for (int v = tid; v < 256; v += 128) { lnws[v] = lnw[v]; lnbs[v] = lnb[v]; }
    cp_wait<0>();
    __syncthreads();

    // LN stats: warp w handles rows w*16 .. w*16+15
    for (int rr = 0; rr < 16; rr++) {
        int r = warp * 16 + rr;
        const float* row = &X[r * X_PITCH];
        float s1 = 0.f, s2 = 0.f;
        #pragma unroll
        for (int e = 0; e < 8; e++) {
            float v = row[e * 32 + lane];
            s1 += v; s2 += v * v;
        }
        #pragma unroll
        for (int o = 16; o; o >>= 1) {
            s1 += __shfl_xor_sync(0xffffffffu, s1, o);
            s2 += __shfl_xor_sync(0xffffffffu, s2, o);
        }
        if (lane == 0) {
            float mu = s1 * (1.f / 256.f);
            float var = s2 * (1.f / 256.f) - mu * mu;
            mus_s[r] = mu;
            rss_s[r] = rsqrtf(var + 1e-5f);
        }
    }
    __syncthreads();

    float mus[2][2], rss[2][2];
    #pragma unroll
    for (int mt = 0; mt < 2; mt++) {
        int r = wm + mt * 16 + g;
        mus[mt][0] = mus_s[r];     rss[mt][0] = rss_s[r];
        mus[mt][1] = mus_s[r + 8]; rss[mt][1] = rss_s[r + 8];
    }

    float acc[2][4][4];
    #pragma unroll
    for (int nt = 0; nt < 4; nt++) {
        int c = wn + nt * 8 + q * 2;
        float b0 = (c < 32) ? bl[c] : br[c - 32];
        float b1 = (c + 1 < 32) ? bl[c + 1] : br[c + 1 - 32];
        #pragma unroll
        for (int mt = 0; mt < 2; mt++) {
            acc[mt][nt][0] = b0; acc[mt][nt][1] = b1;
            acc[mt][nt][2] = b0; acc[mt][nt][3] = b1;
        }
    }

    // mma over 16 k16-steps from resident X
    #pragma unroll
    for (int ks = 0; ks < 16; ks++) {
        int kg = ks * 16;
        int k0 = kg + 2 * q;
        int k1 = k0 + 8;
        float w00 = lnws[k0],     w01 = lnws[k0 + 1];
        float w10 = lnws[k1],     w11 = lnws[k1 + 1];
        float c00 = lnbs[k0],     c01 = lnbs[k0 + 1];
        float c10 = lnbs[k1],     c11 = lnbs[k1 + 1];

        unsigned ah[2][4];
        #pragma unroll
        for (int mt = 0; mt < 2; mt++) {
            int r0 = wm + mt * 16 + g;
            int r1 = r0 + 8;
            float mu0 = mus[mt][0], rs0 = rss[mt][0];
            float mu1 = mus[mt][1], rs1 = rss[mt][1];
            ah[mt][0] = packh2((X[r0 * X_PITCH + k0]     - mu0) * rs0 * w00 + c00,
                               (X[r0 * X_PITCH + k0 + 1] - mu0) * rs0 * w01 + c01);
            ah[mt][1] = packh2((X[r1 * X_PITCH + k0]     - mu1) * rs1 * w00 + c00,
                               (X[r1 * X_PITCH + k0 + 1] - mu1) * rs1 * w01 + c01);
            ah[mt][2] = packh2((X[r0 * X_PITCH + k1]     - mu0) * rs0 * w10 + c10,
                               (X[r0 * X_PITCH + k1 + 1] - mu0) * rs0 * w11 + c11);
            ah[mt][3] = packh2((X[r1 * X_PITCH + k1]     - mu1) * rs1 * w10 + c10,
                               (X[r1 * X_PITCH + k1 + 1] - mu1) * rs1 * w11 + c11);
        }
        unsigned bh[4][2];
        #pragma unroll
        for (int nt = 0; nt < 4; nt++) {
            int n = wn + nt * 8 + g;
            bh[nt][0] = *(const unsigned*)&Wt[n * WT_PITCH + kg + 2 * q];
            bh[nt][1] = *(const unsigned*)&Wt[n * WT_PITCH + kg + 2 * q + 8];
        }
        #pragma unroll
        for (int mt = 0; mt < 2; mt++)
            #pragma unroll
            for (int nt = 0; nt < 4; nt++)
                mma_f16(acc[mt][nt], ah[mt][0], ah[mt][1], ah[mt][2], ah[mt][3],
                        bh[nt][0], bh[nt][1]);
    }
    __syncthreads();

    // epilogue: transpose via smem (overlay on X), write fp16 [m][s]
    __half* T = (__half*)X;                  // [64 cols][72 s] half
    #pragma unroll
    for (int mt = 0; mt < 2; mt++) {
        #pragma unroll
        for (int rr = 0; rr < 2; rr++) {
            int lr = wm + mt * 16 + g + rr * 8;
            #pragma unroll
            for (int nt = 0; nt < 4; nt++) {
                int col = wn + nt * 8 + q * 2;
                float v0 = acc[mt][nt][rr * 2], v1 = acc[mt][nt][rr * 2 + 1];
                if (col < 32) { v0 *= (1.f / 128.f); v1 *= (1.f / 128.f); }
                T[col * 72 + lr]       = __float2half(v0);
                T[(col + 1) * 72 + lr] = __float2half(v1);
            }
        }
    }
    __syncthreads();
    {
        int col = tid >> 1, sh = (tid & 1) * 32;
        const int4* src = (const int4*)&T[col * 72 + sh];
        __half* dst = (col < 32)
            ? &g_Ah[(size_t)(i * 32 + col) * S_DIM + s0 + sh]
            : &g_Bh[(size_t)(i * 32 + (col - 32)) * S_DIM + s0 + sh];
        int4* d4 = (int4*)dst;
        d4[0] = src[0]; d4[1] = src[1]; d4[2] = src[2]; d4[3] = src[3];
    }
}

// ---------------------------------------------------------------------------
// Kernel 2: outer GEMM (fp16)  S[m][n] = sum_s Ah[m][s] * Bh[n][s]
//   K = 128 in TWO 64-wide chunks, double-buffered. (R13-best, frozen)
// ---------------------------------------------------------------------------
__global__ __launch_bounds__(256, 2) void k_outer()
{
    extern __shared__ __half smh[];

    const int tid  = threadIdx.x;
    const int warp = tid >> 5, lane = tid & 31;
    const int g = lane >> 2, q = lane & 3;
    const int wm = (warp >> 2) * 64, wn = (warp & 3) * 32;
    const int m0 = blockIdx.x * 128, n0 = blockIdx.y * 128;

    const int mat  = lane >> 3;
    const int lrow = (mat & 1) * 8 + (lane & 7);
    const int lcol = (mat >> 1) * 8;

    auto load = [&](int kc, int st) {
        #pragma unroll
        for (int it = 0; it < 4; it++) {
            int v = tid + it * 256;                 // 0..1023
            int r = v >> 3, ks = (v & 7) << 3;
            cp16(&smh[st * 9216 + r * 72 + ks],
                 &g_Ah[(size_t)(m0 + r) * S_DIM + kc * 64 + ks]);
            cp16(&smh[18432 + st * 9216 + r * 72 + ks],
                 &g_Bh[(size_t)(n0 + r) * S_DIM + kc * 64 + ks]);
        }
        cp_commit();
    };

    load(0, 0);
    load(1, 1);

    float acc[4][4][4];
    #pragma unroll
    for (int a = 0; a < 4; a++)
        #pragma unroll
        for (int b = 0; b < 4; b++)
            #pragma unroll
            for (int c = 0; c < 4; c++) acc[a][b][c] = 0.f;

    #pragma unroll
    for (int kc = 0; kc < 2; kc++) {
        if (kc == 0) cp_wait<1>(); else cp_wait<0>();
        __syncthreads();
        const unsigned Ab = (unsigned)__cvta_generic_to_shared(&smh[kc * 9216]);
        const unsigned Bb = (unsigned)__cvta_generic_to_shared(&smh[18432 + kc * 9216]);
        #pragma unroll
        for (int kk = 0; kk < 4; kk++) {
            unsigned af[4][4], bf[4][2];
            #pragma unroll
            for (int mt = 0; mt < 4; mt++) {
                unsigned a = Ab + (unsigned)(((wm + mt * 16 + lrow) * 72 + kk * 16 + lcol) * 2);
                ldsm4(af[mt][0], af[mt][1], af[mt][2], af[mt][3], a);
            }
            #pragma unroll
            for (int p = 0; p < 2; p++) {
                unsigned a = Bb + (unsigned)(((wn + p * 16 + lrow) * 72 + kk * 16 + lcol) * 2);
                ldsm4(bf[2*p][0], bf[2*p+1][0], bf[2*p][1], bf[2*p+1][1], a);
            }
            #pragma unroll
            for (int mt = 0; mt < 4; mt++)
                #pragma unroll
                for (int nt = 0; nt < 4; nt++)
                    mma_f16(acc[mt][nt], af[mt][0], af[mt][1], af[mt][2], af[mt][3],
                            bf[nt][0], bf[nt][1]);
        }
    }

    __syncthreads();
    __half* St = smh;
    #pragma unroll
    for (int mt = 0; mt < 4; mt++) {
        int r0 = wm + mt * 16 + g;
        #pragma unroll
        for (int nt = 0; nt < 4; nt++) {
            int c = wn + nt * 8 + q * 2;
            __half2 h0, h1;
            h0.x = __float2half(acc[mt][nt][0]); h0.y = __float2half(acc[mt][nt][1]);
            h1.x = __float2half(acc[mt][nt][2]); h1.y = __float2half(acc[mt][nt][3]);
            *(__half2*)&St[r0 * 136 + c]       = h0;
            *(__half2*)&St[(r0 + 8) * 136 + c] = h1;
        }
    }
    __syncthreads();
    #pragma unroll
    for (int it = 0; it < 8; it++) {
        int t = tid + it * 256;                 // 0..2047
        int r = t >> 4, seg = t & 15;
        int4 w = *(const int4*)&St[r * 136 + seg * 8];
        *(int4*)&g_S16[(size_t)(m0 + r) * M1 + n0 + seg * 8] = w;
    }
}

// ---------------------------------------------------------------------------
// Kernel 3 (fp16): out = S_flat @ woT^T + bo.  (R13-best, frozen)
// ---------------------------------------------------------------------------
__global__ __launch_bounds__(256, 2) void k_proj2(const float* __restrict__ bo,
                                                  float* __restrict__ out)
{
    extern __shared__ __half smh[];

    const int tid  = threadIdx.x;
    const int warp = tid >> 5, lane = tid & 31;
    const int g = lane >> 2, q = lane & 3;
    const int wm = (warp >> 2) * 64, wn = (warp & 3) * 32;
    const int jb = blockIdx.x, i = blockIdx.y;

    const int mat  = lane >> 3;
    const int lrow = (mat & 1) * 8 + (lane & 7);
    const int lcol = (mat >> 1) * 8;

    float acc[4][4][4];
    #pragma unroll
    for (int a = 0; a < 4; a++)
        #pragma unroll
        for (int b = 0; b < 4; b++)
            #pragma unroll
            for (int c = 0; c < 4; c++) acc[a][b][c] = 0.f;

    auto issue = [&](int kc, int st) {
        #pragma unroll
        for (int it = 0; it < 4; it++) {
            int v = tid + it * 256;                 // 0..1023
            int r = v >> 3, ks = (v & 7) << 3;
            int cc = 2 * kc + (ks >> 5), d = ks & 31;
            cp16(&smh[st * 9216 + r * 72 + ks],
                 &g_S16[(size_t)(i * 32 + cc) * M1 + jb * 4096 + r * 32 + d]);
            cp16(&smh[27648 + st * 9216 + r * 72 + ks], &g_woT[r * 1024 + kc * 64 + ks]);
        }
        cp_commit();
    };

    issue(0, 0); issue(1, 1); issue(2, 2);
    for (int kc = 0; kc < 16; kc++) {
        int left = 15 - kc;
        if (left >= 2)      cp_wait<2>();
        else if (left == 1) cp_wait<1>();
        else                cp_wait<0>();
        __syncthreads();
        int st = kc % 3;
        const unsigned Ab = (unsigned)__cvta_generic_to_shared(&smh[st * 9216]);
        const unsigned Bb = (unsigned)__cvta_generic_to_shared(&smh[27648 + st * 9216]);
        #pragma unroll
        for (int kk = 0; kk < 4; kk++) {
            unsigned af[4][4], bf[4][2];
            #pragma unroll
            for (int mt = 0; mt < 4; mt++) {
                unsigned a = Ab + (unsigned)(((wm + mt * 16 + lrow) * 72 + kk * 16 + lcol) * 2);
                ldsm4(af[mt][0], af[mt][1], af[mt][2], af[mt][3], a);
            }
            #pragma unroll
            for (int p = 0; p < 2; p++) {
                unsigned a = Bb + (unsigned)(((wn + p * 16 + lrow) * 72 + kk * 16 + lcol) * 2);
                ldsm4(bf[2*p][0], bf[2*p+1][0], bf[2*p][1], bf[2*p+1][1], a);
            }
            #pragma unroll
            for (int mt = 0; mt < 4; mt++)
                #pragma unroll
                for (int nt = 0; nt < 4; nt++)
                    mma_f16(acc[mt][nt], af[mt][0], af[mt][1], af[mt][2], af[mt][3],
                            bf[nt][0], bf[nt][1]);
        }
        __syncthreads();
        if (kc + 3 < 16) issue(kc + 3, st);
    }

    #pragma unroll
    for (int mt = 0; mt < 4; mt++) {
        int j = jb * 128 + wm + mt * 16 + g;
        #pragma unroll
        for (int nt = 0; nt < 4; nt++) {
            int z = wn + nt * 8 + q * 2;
            float b0 = __ldg(&bo[z]), b1 = __ldg(&bo[z + 1]);
            float2 v0, v1;
            v0.x = acc[mt][nt][0] + b0; v0.y = acc[mt][nt][1] + b1;
            v1.x = acc[mt][nt][2] + b0; v1.y = acc[mt][nt][3] + b1;
            *(float2*)&out[(size_t)(i * 256 + j) * 128 + z]     = v0;
            *(float2*)&out[(size_t)(i * 256 + j + 8) * 128 + z] = v1;
        }
    }
}

// ---------------------------------------------------------------------------
extern "C" void kernel_launch(void* const* d_in, const int* in_sizes, int n_in,
                              void* d_out, int out_size)
{
    const float* x   = (const float*)d_in[0];
    const float* lnw = (const float*)d_in[1];
    const float* lnb = (const float*)d_in[2];
    const float* wl  = (const float*)d_in[3];
    const float* bl  = (const float*)d_in[4];
    const float* wr  = (const float*)d_in[5];
    const float* br  = (const float*)d_in[6];
    const float* wo  = (const float*)d_in[7];
    const float* bo  = (const float*)d_in[8];

    const int SMP = 33792 + 66560 + 2048 + 512;    // 102912 B (2 CTAs/SM)
    const int SM2 = 4 * 9216 * 2;                  // 73728 B  (2 CTAs/SM)
    const int SM3 = 6 * 9216 * 2;                  // 110592 B (2 CTAs/SM)

    cudaFuncSetAttribute(k_proj,  cudaFuncAttributeMaxDynamicSharedMemorySize, SMP);
    cudaFuncSetAttribute(k_outer, cudaFuncAttributeMaxDynamicSharedMemorySize, SM2);
    cudaFuncSetAttribute(k_proj2, cudaFuncAttributeMaxDynamicSharedMemorySize, SM3);

    k_prep<<<136, 256>>>(wo, wl, wr);
    k_proj<<<512, 128, SMP>>>(x, lnw, lnb, bl, br);
    k_outer<<<dim3(64, 64), 256, SM2>>>();
    k_proj2<<<dim3(2, 256), 256, SM3>>>(bo, (float*)d_out);
}

// round 15
// speedup vs baseline: 1.0150x; 1.0150x over previous
#include <cuda_runtime.h>
#include <cuda_fp16.h>
#include <cstdint>

#define S_DIM 128
#define I_DIM 256
#define CM    256
#define CC    32
#define CZ    128
#define M1    8192   // I_DIM * CC
#define NROWS 32768  // S_DIM * I_DIM

// Scratch (device globals: allocation-free per harness rules)
__device__ __half g_Ah[(size_t)M1 * S_DIM];     // [(i,c)][s]  A/128, fp16
__device__ __half g_Bh[(size_t)M1 * S_DIM];     // [(j,d)][s]  B,     fp16
__device__ __half g_S16[(size_t)M1 * M1];       // outer [(i,c)][(j,d)], fp16
__device__ __half g_woT[CZ * 1024];             // [z][(c,d)] fp16 transposed w_out
__device__ __half g_WlrT[64 * CM];              // [col(0..63)][k] fp16 (wl|wr)^T
__device__ float  g_mu[NROWS];
__device__ float  g_rs[NROWS];

// ---------------------------------------------------------------------------
// helpers
// ---------------------------------------------------------------------------
__device__ __forceinline__ void cp16(void* s, const void* g) {
    unsigned sa = (unsigned)__cvta_generic_to_shared(s);
    asm volatile("cp.async.cg.shared.global [%0], [%1], 16;\n" :: "r"(sa), "l"(g));
}
__device__ __forceinline__ void cp_commit() { asm volatile("cp.async.commit_group;\n"); }
template<int N> __device__ __forceinline__ void cp_wait() {
    asm volatile("cp.async.wait_group %0;\n" :: "n"(N));
}

__device__ __forceinline__ void stg_cs(void* p, int4 w) {
    asm volatile("st.global.cs.v4.b32 [%0], {%1,%2,%3,%4};"
        :: "l"(p), "r"(w.x), "r"(w.y), "r"(w.z), "r"(w.w) : "memory");
}
__device__ __forceinline__ void stg_cs2(void* p, float2 v) {
    asm volatile("st.global.cs.v2.b32 [%0], {%1,%2};"
        :: "l"(p), "f"(v.x), "f"(v.y) : "memory");
}

__device__ __forceinline__ void ldsm4(unsigned& r0, unsigned& r1, unsigned& r2, unsigned& r3,
                                      unsigned addr) {
    asm volatile("ldmatrix.sync.aligned.m8n8.x4.shared.b16 {%0,%1,%2,%3}, [%4];"
        : "=r"(r0), "=r"(r1), "=r"(r2), "=r"(r3) : "r"(addr));
}

__device__ __forceinline__ void mma_f16(float c[4],
                                        unsigned a0, unsigned a1, unsigned a2, unsigned a3,
                                        unsigned b0, unsigned b1) {
    asm volatile(
        "mma.sync.aligned.m16n8k16.row.col.f32.f16.f16.f32 "
        "{%0,%1,%2,%3}, {%4,%5,%6,%7}, {%8,%9}, {%0,%1,%2,%3};"
        : "+f"(c[0]), "+f"(c[1]), "+f"(c[2]), "+f"(c[3])
        : "r"(a0), "r"(a1), "r"(a2), "r"(a3), "r"(b0), "r"(b1));
}

__device__ __forceinline__ unsigned packh2(float a, float b) {
    __half2 h = __floats2half2_rn(a, b);
    return *(unsigned*)&h;
}

// ---------------------------------------------------------------------------
// Kernel 0 (merged prep): LN stats + w_out transpose + (wl|wr) transpose.
// ---------------------------------------------------------------------------
__global__ __launch_bounds__(256) void k_prep(
    const float* __restrict__ x,  const float* __restrict__ wo,
    const float* __restrict__ wl, const float* __restrict__ wr)
{
    const int bid = blockIdx.x;
    const int tid = threadIdx.x;
    if (bid < 4096) {
        const int row  = bid * 8 + (tid >> 5);
        const int lane = tid & 31;
        const float4* p = (const float4*)(x + (size_t)row * CM);
        float4 u = p[lane], v = p[lane + 32];
        float s1 = u.x + u.y + u.z + u.w + v.x + v.y + v.z + v.w;
        float s2 = u.x*u.x + u.y*u.y + u.z*u.z + u.w*u.w
                 + v.x*v.x + v.y*v.y + v.z*v.z + v.w*v.w;
        #pragma unroll
        for (int o = 16; o; o >>= 1) {
            s1 += __shfl_xor_sync(0xffffffffu, s1, o);
            s2 += __shfl_xor_sync(0xffffffffu, s2, o);
        }
        if (lane == 0) {
            float mu  = s1 * (1.f / 256.f);
            float var = s2 * (1.f / 256.f) - mu * mu;
            g_mu[row] = mu;
            g_rs[row] = rsqrtf(var + 1e-5f);
        }
    } else if (bid < 4224) {
        const int z = bid - 4096;
        for (int k = tid; k < 1024; k += 256)
            g_woT[z * 1024 + k] = __float2half(wo[k * CZ + z]);
    } else {
        const int base = (bid - 4224) * 2048;
        for (int t = tid; t < 2048; t += 256) {
            int e = base + t;
            int c = e >> 8, k = e & 255;
            float v = (c < 32) ? wl[k * CC + c] : wr[k * CC + (c - 32)];
            g_WlrT[c * CM + k] = __float2half(v);
        }
    }
}

// ---------------------------------------------------------------------------
// Kernel 1: LN + dual projection via fp16 tensor cores (m16n8k16).
//   (R13-best, frozen: streaming x double-buffered, stats from g_mu/g_rs)
// ---------------------------------------------------------------------------
#define WT_PITCH 264   // halves per Wt row

__global__ __launch_bounds__(128, 3) void k_proj(
    const float* __restrict__ x, const float* __restrict__ lnw, const float* __restrict__ lnb,
    const float* __restrict__ bl, const float* __restrict__ br)
{
    extern __shared__ char smc[];
    __half* Wt   = (__half*)smc;                        // [64][264] halves
    float*  xs   = (float*)(smc + 33792);               // 2 x [64][36]
    float*  lnws = (float*)(smc + 33792 + 18432);       // 256
    float*  lnbs = lnws + 256;                          // 256

    const int tid  = threadIdx.x;
    const int warp = tid >> 5, lane = tid & 31;
    const int g = lane >> 2, q = lane & 3;
    const int wm = (warp >> 1) * 32, wn = (warp & 1) * 32;
    const int m0 = blockIdx.x * 64;
    const int i  = m0 >> 7;
    const int s0 = m0 & 127;

    #pragma unroll
    for (int it = 0; it < 16; it++) {
        int v = tid + it * 128;                 // 0..2047
        int row = v >> 5, seg = v & 31;
        cp16(&Wt[row * WT_PITCH + seg * 8], &g_WlrT[row * CM + seg * 8]);
    }
    cp_commit();
    for (int v = tid; v < 256; v += 128) { lnws[v] = lnw[v]; lnbs[v] = lnb[v]; }

    float mus[2][2], rss[2][2];
    #pragma unroll
    for (int mt = 0; mt < 2; mt++) {
        int s = s0 + wm + mt * 16 + g;
        mus[mt][0] = g_mu[s * 256 + i];       rss[mt][0] = g_rs[s * 256 + i];
        mus[mt][1] = g_mu[(s + 8) * 256 + i]; rss[mt][1] = g_rs[(s + 8) * 256 + i];
    }

    float acc[2][4][4];
    #pragma unroll
    for (int nt = 0; nt < 4; nt++) {
        int c = wn + nt * 8 + q * 2;
        float b0 = (c < 32) ? bl[c] : br[c - 32];
        float b1 = (c + 1 < 32) ? bl[c + 1] : br[c + 1 - 32];
        #pragma unroll
        for (int mt = 0; mt < 2; mt++) {
            acc[mt][nt][0] = b0; acc[mt][nt][1] = b1;
            acc[mt][nt][2] = b0; acc[mt][nt][3] = b1;
        }
    }

    auto issue = [&](int kc, int buf) {
        #pragma unroll
        for (int it = 0; it < 4; it++) {
            int v = tid + it * 128;
            int r = v >> 3, k4 = (v & 7) << 2;
            cp16(&xs[buf * 2304 + r * 36 + k4],
                 &x[(size_t)((s0 + r) * 256 + i) * CM + kc * 32 + k4]);
        }
        cp_commit();
    };

    issue(0, 0);
    int buf = 0;
    for (int kc = 0; kc < 8; kc++) {
        if (kc < 7) { issue(kc + 1, buf ^ 1); cp_wait<1>(); }
        else        { cp_wait<0>(); }
        __syncthreads();
        const float* X = &xs[buf * 2304];
        #pragma unroll
        for (int ks = 0; ks < 2; ks++) {
            int kb = ks * 16;
            int kg = kc * 32 + kb;
            int k0 = kb + 2 * q;
            int k1 = k0 + 8;
            float w00 = lnws[kg + 2*q],     w01 = lnws[kg + 2*q + 1];
            float w10 = lnws[kg + 2*q + 8], w11 = lnws[kg + 2*q + 9];
            float c00 = lnbs[kg + 2*q],     c01 = lnbs[kg + 2*q + 1];
            float c10 = lnbs[kg + 2*q + 8], c11 = lnbs[kg + 2*q + 9];

            unsigned ah[2][4];
            #pragma unroll
            for (int mt = 0; mt < 2; mt++) {
                int r0 = wm + mt * 16 + g;
                int r1 = r0 + 8;
                float mu0 = mus[mt][0], rs0 = rss[mt][0];
                float mu1 = mus[mt][1], rs1 = rss[mt][1];
                ah[mt][0] = packh2((X[r0 * 36 + k0]     - mu0) * rs0 * w00 + c00,
                                   (X[r0 * 36 + k0 + 1] - mu0) * rs0 * w01 + c01);
                ah[mt][1] = packh2((X[r1 * 36 + k0]     - mu1) * rs1 * w00 + c00,
                                   (X[r1 * 36 + k0 + 1] - mu1) * rs1 * w01 + c01);
                ah[mt][2] = packh2((X[r0 * 36 + k1]     - mu0) * rs0 * w10 + c10,
                                   (X[r0 * 36 + k1 + 1] - mu0) * rs0 * w11 + c11);
                ah[mt][3] = packh2((X[r1 * 36 + k1]     - mu1) * rs1 * w10 + c10,
                                   (X[r1 * 36 + k1 + 1] - mu1) * rs1 * w11 + c11);
            }
            unsigned bh[4][2];
            #pragma unroll
            for (int nt = 0; nt < 4; nt++) {
                int n = wn + nt * 8 + g;
                bh[nt][0] = *(const unsigned*)&Wt[n * WT_PITCH + kg + 2 * q];
                bh[nt][1] = *(const unsigned*)&Wt[n * WT_PITCH + kg + 2 * q + 8];
            }
            #pragma unroll
            for (int mt = 0; mt < 2; mt++)
                #pragma unroll
                for (int nt = 0; nt < 4; nt++)
                    mma_f16(acc[mt][nt], ah[mt][0], ah[mt][1], ah[mt][2], ah[mt][3],
                            bh[nt][0], bh[nt][1]);
        }
        __syncthreads();
        buf ^= 1;
    }

    // epilogue: transpose via smem (overlay on xs), write fp16 [m][s]
    __half* T = (__half*)xs;                 // [64 cols][72 s] half
    #pragma unroll
    for (int mt = 0; mt < 2; mt++) {
        #pragma unroll
        for (int rr = 0; rr < 2; rr++) {
            int lr = wm + mt * 16 + g + rr * 8;
            #pragma unroll
            for (int nt = 0; nt < 4; nt++) {
                int col = wn + nt * 8 + q * 2;
                float v0 = acc[mt][nt][rr * 2], v1 = acc[mt][nt][rr * 2 + 1];
                if (col < 32) { v0 *= (1.f / 128.f); v1 *= (1.f / 128.f); }
                T[col * 72 + lr]       = __float2half(v0);
                T[(col + 1) * 72 + lr] = __float2half(v1);
            }
        }
    }
    __syncthreads();
    {
        int col = tid >> 1, sh = (tid & 1) * 32;
        const int4* src = (const int4*)&T[col * 72 + sh];
        __half* dst = (col < 32)
            ? &g_Ah[(size_t)(i * 32 + col) * S_DIM + s0 + sh]
            : &g_Bh[(size_t)(i * 32 + (col - 32)) * S_DIM + s0 + sh];
        int4* d4 = (int4*)dst;
        d4[0] = src[0]; d4[1] = src[1]; d4[2] = src[2]; d4[3] = src[3];
    }
}

// ---------------------------------------------------------------------------
// Kernel 2: outer GEMM (fp16)  S[m][n] = sum_s Ah[m][s] * Bh[n][s]
//   K = 128 in TWO 64-wide chunks, double-buffered. S16 stores use .cs
//   (evict-first) to keep Ah/Bh/woT resident in L2.
// ---------------------------------------------------------------------------
__global__ __launch_bounds__(256, 2) void k_outer()
{
    extern __shared__ __half smh[];

    const int tid  = threadIdx.x;
    const int warp = tid >> 5, lane = tid & 31;
    const int g = lane >> 2, q = lane & 3;
    const int wm = (warp >> 2) * 64, wn = (warp & 3) * 32;
    const int m0 = blockIdx.x * 128, n0 = blockIdx.y * 128;

    const int mat  = lane >> 3;
    const int lrow = (mat & 1) * 8 + (lane & 7);
    const int lcol = (mat >> 1) * 8;

    auto load = [&](int kc, int st) {
        #pragma unroll
        for (int it = 0; it < 4; it++) {
            int v = tid + it * 256;                 // 0..1023
            int r = v >> 3, ks = (v & 7) << 3;      // row, k offset (halves)
            cp16(&smh[st * 9216 + r * 72 + ks],
                 &g_Ah[(size_t)(m0 + r) * S_DIM + kc * 64 + ks]);
            cp16(&smh[18432 + st * 9216 + r * 72 + ks],
                 &g_Bh[(size_t)(n0 + r) * S_DIM + kc * 64 + ks]);
        }
        cp_commit();
    };

    load(0, 0);
    load(1, 1);

    float acc[4][4][4];
    #pragma unroll
    for (int a = 0; a < 4; a++)
        #pragma unroll
        for (int b = 0; b < 4; b++)
            #pragma unroll
            for (int c = 0; c < 4; c++) acc[a][b][c] = 0.f;

    #pragma unroll
    for (int kc = 0; kc < 2; kc++) {
        if (kc == 0) cp_wait<1>(); else cp_wait<0>();
        __syncthreads();
        const unsigned Ab = (unsigned)__cvta_generic_to_shared(&smh[kc * 9216]);
        const unsigned Bb = (unsigned)__cvta_generic_to_shared(&smh[18432 + kc * 9216]);
        #pragma unroll
        for (int kk = 0; kk < 4; kk++) {
            unsigned af[4][4], bf[4][2];
            #pragma unroll
            for (int mt = 0; mt < 4; mt++) {
                unsigned a = Ab + (unsigned)(((wm + mt * 16 + lrow) * 72 + kk * 16 + lcol) * 2);
                ldsm4(af[mt][0], af[mt][1], af[mt][2], af[mt][3], a);
            }
            #pragma unroll
            for (int p = 0; p < 2; p++) {
                unsigned a = Bb + (unsigned)(((wn + p * 16 + lrow) * 72 + kk * 16 + lcol) * 2);
                ldsm4(bf[2*p][0], bf[2*p+1][0], bf[2*p][1], bf[2*p+1][1], a);
            }
            #pragma unroll
            for (int mt = 0; mt < 4; mt++)
                #pragma unroll
                for (int nt = 0; nt < 4; nt++)
                    mma_f16(acc[mt][nt], af[mt][0], af[mt][1], af[mt][2], af[mt][3],
                            bf[nt][0], bf[nt][1]);
        }
    }

    // epilogue: stage fp16 S tile in smh[0..17408) (pitch 136), then
    // coalesced evict-first stores.
    __syncthreads();
    __half* St = smh;
    #pragma unroll
    for (int mt = 0; mt < 4; mt++) {
        int r0 = wm + mt * 16 + g;
        #pragma unroll
        for (int nt = 0; nt < 4; nt++) {
            int c = wn + nt * 8 + q * 2;
            __half2 h0, h1;
            h0.x = __float2half(acc[mt][nt][0]); h0.y = __float2half(acc[mt][nt][1]);
            h1.x = __float2half(acc[mt][nt][2]); h1.y = __float2half(acc[mt][nt][3]);
            *(__half2*)&St[r0 * 136 + c]       = h0;
            *(__half2*)&St[(r0 + 8) * 136 + c] = h1;
        }
    }
    __syncthreads();
    #pragma unroll
    for (int it = 0; it < 8; it++) {
        int t = tid + it * 256;                 // 0..2047
        int r = t >> 4, seg = t & 15;
        int4 w = *(const int4*)&St[r * 136 + seg * 8];
        stg_cs(&g_S16[(size_t)(m0 + r) * M1 + n0 + seg * 8], w);
    }
}

// ---------------------------------------------------------------------------
// Kernel 3 (fp16): out = S_flat @ woT^T + bo. 3-stage pipeline (R13-best);
// out stores evict-first (never re-read).
// ---------------------------------------------------------------------------
__global__ __launch_bounds__(256, 2) void k_proj2(const float* __restrict__ bo,
                                                  float* __restrict__ out)
{
    extern __shared__ __half smh[];

    const int tid  = threadIdx.x;
    const int warp = tid >> 5, lane = tid & 31;
    const int g = lane >> 2, q = lane & 3;
    const int wm = (warp >> 2) * 64, wn = (warp & 3) * 32;
    const int jb = blockIdx.x, i = blockIdx.y;

    const int mat  = lane >> 3;
    const int lrow = (mat & 1) * 8 + (lane & 7);
    const int lcol = (mat >> 1) * 8;

    float acc[4][4][4];
    #pragma unroll
    for (int a = 0; a < 4; a++)
        #pragma unroll
        for (int b = 0; b < 4; b++)
            #pragma unroll
            for (int c = 0; c < 4; c++) acc[a][b][c] = 0.f;

    auto issue = [&](int kc, int st) {
        #pragma unroll
        for (int it = 0; it < 4; it++) {
            int v = tid + it * 256;                 // 0..1023
            int r = v >> 3, ks = (v & 7) << 3;      // row, k offset in chunk (halves)
            int cc = 2 * kc + (ks >> 5), d = ks & 31;
            cp16(&smh[st * 9216 + r * 72 + ks],
                 &g_S16[(size_t)(i * 32 + cc) * M1 + jb * 4096 + r * 32 + d]);
            cp16(&smh[27648 + st * 9216 + r * 72 + ks], &g_woT[r * 1024 + kc * 64 + ks]);
        }
        cp_commit();
    };

    issue(0, 0); issue(1, 1); issue(2, 2);
    for (int kc = 0; kc < 16; kc++) {
        int left = 15 - kc;
        if (left >= 2)      cp_wait<2>();
        else if (left == 1) cp_wait<1>();
        else                cp_wait<0>();
        __syncthreads();
        int st = kc % 3;
        const unsigned Ab = (unsigned)__cvta_generic_to_shared(&smh[st * 9216]);
        const unsigned Bb = (unsigned)__cvta_generic_to_shared(&smh[27648 + st * 9216]);
        #pragma unroll
        for (int kk = 0; kk < 4; kk++) {
            unsigned af[4][4], bf[4][2];
            #pragma unroll
            for (int mt = 0; mt < 4; mt++) {
                unsigned a = Ab + (unsigned)(((wm + mt * 16 + lrow) * 72 + kk * 16 + lcol) * 2);
                ldsm4(af[mt][0], af[mt][1], af[mt][2], af[mt][3], a);
            }
            #pragma unroll
            for (int p = 0; p < 2; p++) {
                unsigned a = Bb + (unsigned)(((wn + p * 16 + lrow) * 72 + kk * 16 + lcol) * 2);
                ldsm4(bf[2*p][0], bf[2*p+1][0], bf[2*p][1], bf[2*p+1][1], a);
            }
            #pragma unroll
            for (int mt = 0; mt < 4; mt++)
                #pragma unroll
                for (int nt = 0; nt < 4; nt++)
                    mma_f16(acc[mt][nt], af[mt][0], af[mt][1], af[mt][2], af[mt][3],
                            bf[nt][0], bf[nt][1]);
        }
        __syncthreads();
        if (kc + 3 < 16) issue(kc + 3, st);
    }

    #pragma unroll
    for (int mt = 0; mt < 4; mt++) {
        int j = jb * 128 + wm + mt * 16 + g;
        #pragma unroll
        for (int nt = 0; nt < 4; nt++) {
            int z = wn + nt * 8 + q * 2;
            float b0 = __ldg(&bo[z]), b1 = __ldg(&bo[z + 1]);
            float2 v0, v1;
            v0.x = acc[mt][nt][0] + b0; v0.y = acc[mt][nt][1] + b1;
            v1.x = acc[mt][nt][2] + b0; v1.y = acc[mt][nt][3] + b1;
            stg_cs2(&out[(size_t)(i * 256 + j) * 128 + z], v0);
            stg_cs2(&out[(size_t)(i * 256 + j + 8) * 128 + z], v1);
        }
    }
}

// ---------------------------------------------------------------------------
extern "C" void kernel_launch(void* const* d_in, const int* in_sizes, int n_in,
                              void* d_out, int out_size)
{
    const float* x   = (const float*)d_in[0];
    const float* lnw = (const float*)d_in[1];
    const float* lnb = (const float*)d_in[2];
    const float* wl  = (const float*)d_in[3];
    const float* bl  = (const float*)d_in[4];
    const float* wr  = (const float*)d_in[5];
    const float* br  = (const float*)d_in[6];
    const float* wo  = (const float*)d_in[7];
    const float* bo  = (const float*)d_in[8];

    const int SMP = 33792 + 18432 + 2048;          // 54272 B  (3 CTAs/SM)
    const int SM2 = 4 * 9216 * 2;                  // 73728 B  (2 CTAs/SM)
    const int SM3 = 6 * 9216 * 2;                  // 110592 B (2 CTAs/SM)

    cudaFuncSetAttribute(k_proj,  cudaFuncAttributeMaxDynamicSharedMemorySize, SMP);
    cudaFuncSetAttribute(k_outer, cudaFuncAttributeMaxDynamicSharedMemorySize, SM2);
    cudaFuncSetAttribute(k_proj2, cudaFuncAttributeMaxDynamicSharedMemorySize, SM3);

    k_prep<<<4232, 256>>>(x, wo, wl, wr);
    k_proj<<<512, 128, SMP>>>(x, lnw, lnb, bl, br);
    k_outer<<<dim3(64, 64), 256, SM2>>>();
    k_proj2<<<dim3(2, 256), 256, SM3>>>(bo, (float*)d_out);
}